// round 1
// baseline (speedup 1.0000x reference)
#include <cuda_runtime.h>

// STDP with TE=1.0: e_{t} = (e_{t-1} - e_{t-1}/1.0) + outer = 0 + outer,
// so the final eligibility depends ONLY on the last timestep:
//   e[i][j] = x_T[i] * q_T[j] - p_T[i] * y_T[j]
// where x_T, y_T are the exponentially filtered traces (x += (p - x)/2).
//
// Kernel A: 2048 per-neuron scalar recurrences over T steps -> g_x, g_y.
// Kernel B: rank-2 outer product difference, float4-vectorized, 4 MB write.

#define N_NEUR 1024

__device__ float g_x[N_NEUR];
__device__ float g_y[N_NEUR];

__global__ void stdp_trace_kernel(const float* __restrict__ pre,
                                  const float* __restrict__ post,
                                  int T) {
    int tid = blockIdx.x * blockDim.x + threadIdx.x;  // 0..2047
    const float* src;
    float* dst;
    int i;
    if (tid < N_NEUR) {
        src = pre;  dst = g_x; i = tid;
    } else {
        src = post; dst = g_y; i = tid - N_NEUR;
    }
    float x = 0.0f;
    // Same rounding order as reference: x = x + (-x + p)/2
    #pragma unroll 8
    for (int t = 0; t < T; t++) {
        float p = src[(size_t)t * N_NEUR + i];
        x = x + (p - x) * 0.5f;
    }
    dst[i] = x;
}

__global__ void stdp_outer_kernel(const float* __restrict__ pre_last,
                                  const float* __restrict__ post_last,
                                  float* __restrict__ e) {
    // One float4 (4 consecutive j) per thread. 1024*256 = 262144 threads.
    int idx = blockIdx.x * blockDim.x + threadIdx.x;
    int i  = idx >> 8;        // row (pre index), 256 float4 per row
    int j4 = idx & 255;       // float4 column index

    float xi = g_x[i];
    float pi = pre_last[i];

    const float4* qv = reinterpret_cast<const float4*>(post_last);
    const float4* yv = reinterpret_cast<const float4*>(g_y);
    float4 q = qv[j4];
    float4 y = yv[j4];

    float4 r;
    r.x = xi * q.x - pi * y.x;
    r.y = xi * q.y - pi * y.y;
    r.z = xi * q.z - pi * y.z;
    r.w = xi * q.w - pi * y.w;

    reinterpret_cast<float4*>(e)[idx] = r;
}

extern "C" void kernel_launch(void* const* d_in, const int* in_sizes, int n_in,
                              void* d_out, int out_size) {
    const float* pre  = (const float*)d_in[0];   // [T, 1024]
    const float* post = (const float*)d_in[1];   // [T, 1024]
    float* e = (float*)d_out;                    // [1024, 1024]

    int T = in_sizes[0] / N_NEUR;                // 256

    // Kernel A: compute traces x_T, y_T (2048 threads)
    stdp_trace_kernel<<<8, 256>>>(pre, post, T);

    // Kernel B: e = x ⊗ q_T - p_T ⊗ y  (262144 threads, float4 stores)
    const float* pre_last  = pre  + (size_t)(T - 1) * N_NEUR;
    const float* post_last = post + (size_t)(T - 1) * N_NEUR;
    int n4 = (N_NEUR * N_NEUR) / 4;              // 262144
    stdp_outer_kernel<<<n4 / 256, 256>>>(pre_last, post_last, e);
}

// round 2
// speedup vs baseline: 2.0673x; 2.0673x over previous
#include <cuda_runtime.h>

// STDP with TE=1.0 collapses: e[i][j] = x_T[i]*q_T[j] - p_T[i]*y_T[j]
// where x,y are EMA traces (v += (s - v)/2). Since 0.5^32 < 2^-31, only the
// last K=32 timesteps contribute above fp32 rounding -> truncate the
// recurrence and fuse everything into ONE kernel.
//
// Grid: 128 blocks x 256 threads. Block b owns output rows [8b, 8b+8).
//  Phase 1a: all 1024 y-traces (exact reference Horner over the K-tail,
//            float4-coalesced loads) -> smem. Redundant across blocks but
//            the 128KB post-tail is L2-resident.
//  Phase 1b: 8 warps compute the block's 8 x-traces as an exact dyadic
//            weighted warp-reduce over the K-tail (uncoalesced but tiny).
//  Phase 2:  rank-2 outer-product difference from smem, float4 stores.

#define N 1024
#define K 32
#define ROWS 8
#define THREADS 256

__global__ __launch_bounds__(THREADS, 1)
void stdp_fused_kernel(const float* __restrict__ pre,
                       const float* __restrict__ post,
                       float* __restrict__ e,
                       int T) {
    __shared__ float sy[N];     // y traces
    __shared__ float sq[N];     // post last row
    __shared__ float sx[ROWS];  // x traces for this block's rows
    __shared__ float sp[ROWS];  // pre last row for this block's rows

    const int tid = threadIdx.x;
    const int i0 = blockIdx.x * ROWS;
    const int k0 = T - K;       // tail start (T=256 >= K)

    // ---- Phase 1a: y traces, 4 consecutive cols per thread ----
    const float4* postv = reinterpret_cast<const float4*>(post);
    const int j4 = tid;         // float4 column index 0..255
    float4 acc = make_float4(0.f, 0.f, 0.f, 0.f);
    #pragma unroll
    for (int t = 0; t < K; t++) {
        float4 q = postv[(size_t)(k0 + t) * (N / 4) + j4];
        // exact reference rounding order: y = y + (q - y) * 0.5
        acc.x = acc.x + (q.x - acc.x) * 0.5f;
        acc.y = acc.y + (q.y - acc.y) * 0.5f;
        acc.z = acc.z + (q.z - acc.z) * 0.5f;
        acc.w = acc.w + (q.w - acc.w) * 0.5f;
    }
    reinterpret_cast<float4*>(sy)[j4] = acc;
    float4 qlast = postv[(size_t)(T - 1) * (N / 4) + j4];
    reinterpret_cast<float4*>(sq)[j4] = qlast;

    // ---- Phase 1b: x traces, one warp per row ----
    const int w = tid >> 5;
    const int lane = tid & 31;
    if (w < ROWS) {
        const int i = i0 + w;
        float p = pre[(size_t)(k0 + lane) * N + i];
        // weight 0.5^(K - lane): exact power of two via exponent bits
        float wt = __int_as_float((127 - (K - lane)) << 23);
        float v = p * wt;   // exact (p in {0,1})
        #pragma unroll
        for (int off = 16; off; off >>= 1)
            v += __shfl_xor_sync(0xffffffffu, v, off);
        if (lane == 0)      sx[w] = v;
        if (lane == K - 1)  sp[w] = p;  // p at t = T-1
    }
    __syncthreads();

    // ---- Phase 2: e[i][j] = x[i]*q[j] - p[i]*y[j] ----
    float4* ev = reinterpret_cast<float4*>(e);
    const float4 q = reinterpret_cast<const float4*>(sq)[j4];
    const float4 y = reinterpret_cast<const float4*>(sy)[j4];
    #pragma unroll
    for (int r = 0; r < ROWS; r++) {
        const float xi = sx[r];
        const float pi = sp[r];
        float4 o;
        o.x = xi * q.x - pi * y.x;
        o.y = xi * q.y - pi * y.y;
        o.z = xi * q.z - pi * y.z;
        o.w = xi * q.w - pi * y.w;
        ev[(size_t)(i0 + r) * (N / 4) + j4] = o;
    }
}

extern "C" void kernel_launch(void* const* d_in, const int* in_sizes, int n_in,
                              void* d_out, int out_size) {
    const float* pre  = (const float*)d_in[0];   // [T, 1024]
    const float* post = (const float*)d_in[1];   // [T, 1024]
    float* e = (float*)d_out;                    // [1024, 1024]
    int T = in_sizes[0] / N;                     // 256

    stdp_fused_kernel<<<N / ROWS, THREADS>>>(pre, post, e, T);
}